// round 4
// baseline (speedup 1.0000x reference)
#include <cuda_runtime.h>
#include <cstdint>

// Problem constants (from reference)
#define TT   8192
#define BB   8
#define DD   512
#define NC   256         // number of chunks along T
#define CL   32          // chunk length = TT/NC
#define DQ   128         // DD/4 float4 lanes
#define C0F  2.0f        // PRIOR_COUNT
#define EPSF 1e-5f

// Scratch: partial (then exclusive-prefix) sums per (chunk, b, d) and counts per (chunk, b).
__device__ float g_psx [NC * BB * DD];   // 4 MB
__device__ float g_psxx[NC * BB * DD];   // 4 MB
__device__ int   g_cnt [NC * BB];

// ---------------------------------------------------------------------------
// Kernel A: per-chunk partial sums of valid*x and valid*x^2, plus valid counts.
// grid = (NC, BB), block = 512 threads: dq = tid&127 (float4 lane over D),
// tq = tid>>7 (t-group 0..3). Each thread does 8 float4 loads (t = tq+4i).
// ---------------------------------------------------------------------------
__global__ void __launch_bounds__(512) tn_partial(
    const float4* __restrict__ x4, const unsigned char* __restrict__ mask)
{
    const int chunk = blockIdx.x;
    const int b     = blockIdx.y;
    const int tid   = threadIdx.x;
    const int dq    = tid & (DQ - 1);
    const int tq    = tid >> 7;          // 0..3

    // float4 index of (t = chunk*CL + tq, b, 4*dq)
    const float4* xp = x4 + ((size_t)(chunk * CL + tq) * BB + b) * DQ + dq;
    const unsigned char* mp = mask + (size_t)b * TT + chunk * CL;
    const int stride4 = 4 * BB * DQ;     // advance t by 4

    float4 sx  = make_float4(0.f, 0.f, 0.f, 0.f);
    float4 sxx = make_float4(0.f, 0.f, 0.f, 0.f);
#pragma unroll
    for (int i = 0; i < CL / 4; ++i) {   // 8 iterations
        float4 v    = xp[(size_t)i * stride4];
        float valid = mp[tq + 4 * i] ? 0.0f : 1.0f;
        float vx = v.x * valid, vy = v.y * valid, vz = v.z * valid, vw = v.w * valid;
        sx.x += vx;  sx.y += vy;  sx.z += vz;  sx.w += vw;
        sxx.x = fmaf(vx, v.x, sxx.x);
        sxx.y = fmaf(vy, v.y, sxx.y);
        sxx.z = fmaf(vz, v.z, sxx.z);
        sxx.w = fmaf(vw, v.w, sxx.w);
    }

    __shared__ float4 s_sx [4][DQ];
    __shared__ float4 s_sxx[4][DQ];
    s_sx [tq][dq] = sx;
    s_sxx[tq][dq] = sxx;
    __syncthreads();

    if (tq == 0) {
#pragma unroll
        for (int g = 1; g < 4; ++g) {
            float4 a = s_sx[g][dq], q = s_sxx[g][dq];
            sx.x += a.x; sx.y += a.y; sx.z += a.z; sx.w += a.w;
            sxx.x += q.x; sxx.y += q.y; sxx.z += q.z; sxx.w += q.w;
        }
        const int ci = (chunk * BB + b) * DQ + dq;
        ((float4*)g_psx )[ci] = sx;
        ((float4*)g_psxx)[ci] = sxx;
    }

    // valid count for this (chunk,b): first warp, one lane per t (CL==32).
    if (tid < 32) {
        unsigned bal = __ballot_sync(0xFFFFFFFFu, mp[tid] == 0);
        if (tid == 0) g_cnt[chunk * BB + b] = __popc(bal);
    }
}

// ---------------------------------------------------------------------------
// Kernel B: exclusive scan across chunks.
// grid = 9 blocks x 128 threads.
//   blocks 0..7: channel quads (1024 float4 channels), serial over 256 chunks.
//   block 8:     counts, warp-parallel scan (4 warps, 2 b each).
// ---------------------------------------------------------------------------
__global__ void __launch_bounds__(128) tn_scan()
{
    if (blockIdx.x < 8) {
        const int id = blockIdx.x * 128 + threadIdx.x;   // 0..1023 float4 channels
        float4* psx4  = (float4*)g_psx;
        float4* psxx4 = (float4*)g_psxx;
        float4 ax  = make_float4(0.f, 0.f, 0.f, 0.f);
        float4 axx = make_float4(0.f, 0.f, 0.f, 0.f);
#pragma unroll 8
        for (int c = 0; c < NC; ++c) {
            const int i = c * (BB * DQ) + id;
            float4 sx = psx4[i], sxx = psxx4[i];
            psx4[i] = ax; psxx4[i] = axx;
            ax.x += sx.x;  ax.y += sx.y;  ax.z += sx.z;  ax.w += sx.w;
            axx.x += sxx.x; axx.y += sxx.y; axx.z += sxx.z; axx.w += sxx.w;
        }
    } else {
        // counts: NC x BB ints. Warp w handles b = w and b = w+4.
        const int lane = threadIdx.x & 31;
        const int warp = threadIdx.x >> 5;
        for (int b = warp; b < BB; b += 4) {
            int v[8], pre[8], s = 0;
#pragma unroll
            for (int j = 0; j < 8; ++j) v[j] = g_cnt[(lane * 8 + j) * BB + b];
#pragma unroll
            for (int j = 0; j < 8; ++j) { pre[j] = s; s += v[j]; }
            int acc = s;
#pragma unroll
            for (int off = 1; off < 32; off <<= 1) {
                int n = __shfl_up_sync(0xFFFFFFFFu, acc, off);
                if (lane >= off) acc += n;
            }
            const int excl = acc - s;
#pragma unroll
            for (int j = 0; j < 8; ++j) g_cnt[(lane * 8 + j) * BB + b] = excl + pre[j];
        }
    }
}

// ---------------------------------------------------------------------------
// Kernel C: final pass. One thread per 4 d-channels; walks CL=32 timesteps
// with float4 loads/stores. 1/cf is scalar (shared across the 4 lanes).
// grid = (NC, BB), block = 128.
// ---------------------------------------------------------------------------
__global__ void __launch_bounds__(128) tn_final(
    const float4* __restrict__ x4,
    const float4* __restrict__ prior_mean,
    const float4* __restrict__ prior_logv,
    const float4* __restrict__ weight,
    const float4* __restrict__ bias,
    const unsigned char* __restrict__ mask,
    float4* __restrict__ out4)
{
    const int chunk = blockIdx.x;
    const int b     = blockIdx.y;
    const int dq    = threadIdx.x;

    const float4 pm = prior_mean[dq];
    const float4 pl = prior_logv[dq];
    const float4 wt = weight[dq];
    const float4 bi = bias[dq];

    const float4 gamma = make_float4(wt.x + 1.f, wt.y + 1.f, wt.z + 1.f, wt.w + 1.f);
    const float4 A  = make_float4(C0F * pm.x, C0F * pm.y, C0F * pm.z, C0F * pm.w);
    const float4 Bc = make_float4(C0F * fmaf(pm.x, pm.x, __expf(pl.x)),
                                  C0F * fmaf(pm.y, pm.y, __expf(pl.y)),
                                  C0F * fmaf(pm.z, pm.z, __expf(pl.z)),
                                  C0F * fmaf(pm.w, pm.w, __expf(pl.w)));

    const int ci = (chunk * BB + b) * DQ + dq;
    float4 P = ((const float4*)g_psx )[ci];
    float4 Q = ((const float4*)g_psxx)[ci];
    float  cf = C0F + (float)g_cnt[chunk * BB + b];

    const int stride4 = BB * DQ;   // advance t by 1
    const float4* xp = x4   + ((size_t)(chunk * CL) * BB + b) * DQ + dq;
    float4*       op = out4 + ((size_t)(chunk * CL) * BB + b) * DQ + dq;
    const unsigned char* mp = mask + (size_t)b * TT + chunk * CL;

#pragma unroll 4
    for (int t = 0; t < CL; ++t) {
        float4 v    = xp[(size_t)t * stride4];
        float valid = mp[t] ? 0.0f : 1.0f;

        cf += valid;
        float vx = v.x * valid, vy = v.y * valid, vz = v.z * valid, vw = v.w * valid;
        P.x += vx; P.y += vy; P.z += vz; P.w += vw;
        Q.x = fmaf(vx, v.x, Q.x); Q.y = fmaf(vy, v.y, Q.y);
        Q.z = fmaf(vz, v.z, Q.z); Q.w = fmaf(vw, v.w, Q.w);

        const float invc = __fdividef(1.0f, cf);   // one RCP per 4 lanes

        float4 y;
        {
            float mean = (A.x + P.x) * invc;
            float M2   = fmaf(-cf, mean * mean, Q.x + Bc.x);
            float rs   = rsqrtf(fmaf(M2, invc, EPSF));
            y.x = fmaf(v.x - mean, rs * gamma.x, bi.x);
        }
        {
            float mean = (A.y + P.y) * invc;
            float M2   = fmaf(-cf, mean * mean, Q.y + Bc.y);
            float rs   = rsqrtf(fmaf(M2, invc, EPSF));
            y.y = fmaf(v.y - mean, rs * gamma.y, bi.y);
        }
        {
            float mean = (A.z + P.z) * invc;
            float M2   = fmaf(-cf, mean * mean, Q.z + Bc.z);
            float rs   = rsqrtf(fmaf(M2, invc, EPSF));
            y.z = fmaf(v.z - mean, rs * gamma.z, bi.z);
        }
        {
            float mean = (A.w + P.w) * invc;
            float M2   = fmaf(-cf, mean * mean, Q.w + Bc.w);
            float rs   = rsqrtf(fmaf(M2, invc, EPSF));
            y.w = fmaf(v.w - mean, rs * gamma.w, bi.w);
        }
        op[(size_t)t * stride4] = y;
    }
}

// ---------------------------------------------------------------------------
// kernel_launch
// Inputs (metadata order): x, prior_mean, prior_logv, weight, bias, padding_mask
// ---------------------------------------------------------------------------
extern "C" void kernel_launch(void* const* d_in, const int* in_sizes, int n_in,
                              void* d_out, int out_size)
{
    const float4* x4          = (const float4*)d_in[0];
    const float4* prior_mean  = (const float4*)d_in[1];
    const float4* prior_logv  = (const float4*)d_in[2];
    const float4* weight      = (const float4*)d_in[3];
    const float4* bias        = (const float4*)d_in[4];
    const unsigned char* mask = (const unsigned char*)d_in[5];
    float4* out4 = (float4*)d_out;

    dim3 grid(NC, BB);
    tn_partial<<<grid, 512>>>(x4, mask);
    tn_scan<<<9, 128>>>();
    tn_final<<<grid, 128>>>(x4, prior_mean, prior_logv, weight, bias, mask, out4);
}